// round 1
// baseline (speedup 1.0000x reference)
#include <cuda_runtime.h>
#include <cstdint>
#include <cstddef>

// ---------------------------------------------------------------------------
// SpatialAttentionLayer: T=8192 tokens, N=24 joints, D=256, H=8 heads, F=32.
//   q = x_n @ Wq[h,n] + bq ; k/v = x_n @ Wk/Wv[h] + b  (per token, per joint)
//   attn over joints per (t,h); concat heads; residual + LayerNorm(6144)
// Strategy: tf32 mma.sync GEMM for all projections (K1), fused
// attention+residual+LN per token (K2). Weights repacked per joint (prep).
// ---------------------------------------------------------------------------

#define T_TOK 8192
#define NJ    24
#define DIM   256
#define NH    8
#define FD    32
#define JD    6144      // NJ*DIM
#define OUTJ  768       // 3*DIM  (Q|K|V columns)

#define BM 128
#define BN 128
#define BK 32
#define APAD 36
#define BPAD 132

#define SMEM1 ((256*BPAD + 2*BM*APAD + BN) * 4)                    // 172544 B
#define SMEM2 ((192*36 + 6144 + 6144 + 24*260 + 16) * 4)           // 101824 B

// Scratch (static __device__ allocation is the sanctioned path)
__device__ float g_Q[(size_t)T_TOK * NH * NJ * FD];   // [t][h][n][f]
__device__ float g_K[(size_t)T_TOK * NH * NJ * FD];
__device__ float g_V[(size_t)T_TOK * NH * NJ * FD];
__device__ float g_Wt[(size_t)NJ * DIM * OUTJ];        // [n][d][j], tf32-rounded
__device__ float g_bias[NJ * OUTJ];                    // [n][j]

__device__ __forceinline__ unsigned f2tf32(float x) {
    unsigned u;
    asm("cvt.rna.tf32.f32 %0, %1;" : "=r"(u) : "f"(x));
    return u;
}

__device__ __forceinline__ void mma_tf32(float* d, const unsigned* a, const unsigned* b) {
    asm volatile(
        "mma.sync.aligned.m16n8k8.row.col.f32.tf32.tf32.f32 "
        "{%0,%1,%2,%3}, {%4,%5,%6,%7}, {%8,%9}, {%0,%1,%2,%3};\n"
        : "+f"(d[0]), "+f"(d[1]), "+f"(d[2]), "+f"(d[3])
        : "r"(a[0]), "r"(a[1]), "r"(a[2]), "r"(a[3]), "r"(b[0]), "r"(b[1]));
}

// ---------------- prep: repack weights (tf32-rounded) + bias ----------------
__global__ void prep_w_kernel(const float* __restrict__ Wq,
                              const float* __restrict__ Wk,
                              const float* __restrict__ Wv) {
    const size_t total = (size_t)NJ * DIM * OUTJ;
    for (size_t i = (size_t)blockIdx.x * blockDim.x + threadIdx.x; i < total;
         i += (size_t)gridDim.x * blockDim.x) {
        int j = (int)(i % OUTJ);
        size_t nd = i / OUTJ;
        int d = (int)(nd % DIM);
        int n = (int)(nd / DIM);
        int h = (j >> 5) & 7;
        int f = j & 31;
        float v;
        if (j < 256)      v = Wq[(((size_t)h * NJ + n) * DIM + d) * FD + f];
        else if (j < 512) v = Wk[((size_t)h * DIM + d) * FD + f];
        else              v = Wv[((size_t)h * DIM + d) * FD + f];
        g_Wt[i] = __uint_as_float(f2tf32(v));
    }
}

__global__ void prep_b_kernel(const float* __restrict__ bq,
                              const float* __restrict__ bk,
                              const float* __restrict__ bv) {
    int i = blockIdx.x * blockDim.x + threadIdx.x;
    if (i < NJ * OUTJ) {
        int n = i / OUTJ, j = i % OUTJ;
        int h = (j >> 5) & 7;
        int f = j & 31;
        float v;
        if (j < 256)      v = bq[(h * NJ + n) * FD + f];
        else if (j < 512) v = bk[h * FD + f];
        else              v = bv[h * FD + f];
        g_bias[i] = v;
    }
}

// ---------------- K1: QKV projection GEMM (tf32 mma.sync) -------------------
// grid = 144 CTAs: (joint 0..23) x (col-block 0..5 of 128).
// B panel (256x128) resident in SMEM; stream 64 M-tiles of 128 tokens.
__global__ void __launch_bounds__(256, 1)
qkv_gemm_kernel(const float* __restrict__ x) {
    extern __shared__ float sm1[];
    float* Bs     = sm1;                    // [256][BPAD]
    float* As     = sm1 + 256 * BPAD;       // [2][BM][APAD]
    float* bias_s = As + 2 * BM * APAD;     // [BN]

    const int bx = blockIdx.x;
    const int njoint = bx / 6;
    const int nblk   = bx % 6;
    const int tid  = threadIdx.x;
    const int warp = tid >> 5, lane = tid & 31;
    const int g = lane >> 2, tg = lane & 3;
    const int wm = warp >> 2;   // 0..1 -> 64 rows
    const int wn = warp & 3;    // 0..3 -> 32 cols

    // Load resident B panel (already tf32-rounded by prep)
    for (int i = tid; i < 256 * 32; i += 256) {   // 8192 float4
        int d = i >> 5, c4 = i & 31;
        float4 v = *(const float4*)&g_Wt[((size_t)njoint * DIM + d) * OUTJ + nblk * BN + c4 * 4];
        *(float4*)&Bs[d * BPAD + c4 * 4] = v;
    }
    if (tid < BN) bias_s[tid] = g_bias[njoint * OUTJ + nblk * BN + tid];

    float acc[4][4][4];
#pragma unroll
    for (int mt = 0; mt < 4; ++mt)
#pragma unroll
        for (int nt = 0; nt < 4; ++nt)
#pragma unroll
            for (int r = 0; r < 4; ++r) acc[mt][nt][r] = 0.f;

    // ---- prologue: load + store chunk 0 (m-tile 0, kb 0) ----
    float4 rA[4];
    {
        const float* base = x + (size_t)njoint * DIM;   // mt=0, kb=0
#pragma unroll
        for (int i = 0; i < 4; ++i) {
            int lin = tid + 256 * i;
            int row = lin >> 3, c4 = lin & 7;
            rA[i] = *(const float4*)&base[(size_t)row * JD + c4 * 4];
        }
#pragma unroll
        for (int i = 0; i < 4; ++i) {
            int lin = tid + 256 * i;
            int row = lin >> 3, c4 = lin & 7;
            float4 v = rA[i];
            v.x = __uint_as_float(f2tf32(v.x));
            v.y = __uint_as_float(f2tf32(v.y));
            v.z = __uint_as_float(f2tf32(v.z));
            v.w = __uint_as_float(f2tf32(v.w));
            *(float4*)&As[row * APAD + c4 * 4] = v;
        }
    }
    __syncthreads();

#pragma unroll 1
    for (int c = 0; c < 512; ++c) {           // chunk = (m-tile c>>3, kb c&7)
        float4 rN[4];
        if (c < 511) {
            int cn = c + 1;
            int mt = cn >> 3, kb = cn & 7;
            const float* base = x + (size_t)mt * BM * JD + njoint * DIM + kb * BK;
#pragma unroll
            for (int i = 0; i < 4; ++i) {
                int lin = tid + 256 * i;
                int row = lin >> 3, c4 = lin & 7;
                rN[i] = *(const float4*)&base[(size_t)row * JD + c4 * 4];
            }
        }

        // ---- compute on stage c&1 ----
        const float* A0 = As + (c & 1) * BM * APAD;
#pragma unroll
        for (int kk = 0; kk < 4; ++kk) {
            unsigned a[4][4], b[4][2];
#pragma unroll
            for (int mt = 0; mt < 4; ++mt) {
                int r0 = wm * 64 + mt * 16;
                a[mt][0] = __float_as_uint(A0[(r0 + g)     * APAD + kk * 8 + tg]);
                a[mt][1] = __float_as_uint(A0[(r0 + 8 + g) * APAD + kk * 8 + tg]);
                a[mt][2] = __float_as_uint(A0[(r0 + g)     * APAD + kk * 8 + tg + 4]);
                a[mt][3] = __float_as_uint(A0[(r0 + 8 + g) * APAD + kk * 8 + tg + 4]);
            }
            int kglob = (c & 7) * BK + kk * 8;
#pragma unroll
            for (int nt = 0; nt < 4; ++nt) {
                int cc = wn * 32 + nt * 8 + g;
                b[nt][0] = __float_as_uint(Bs[(kglob + tg)     * BPAD + cc]);
                b[nt][1] = __float_as_uint(Bs[(kglob + 4 + tg) * BPAD + cc]);
            }
#pragma unroll
            for (int mt = 0; mt < 4; ++mt)
#pragma unroll
                for (int nt = 0; nt < 4; ++nt)
                    mma_tf32(acc[mt][nt], a[mt], b[nt]);
        }

        // ---- epilogue at end of each m-tile ----
        if ((c & 7) == 7) {
            int mtile = c >> 3;
            int base_t = mtile * BM + wm * 64;
#pragma unroll
            for (int mt = 0; mt < 4; ++mt)
#pragma unroll
                for (int nt = 0; nt < 4; ++nt) {
                    int t0 = base_t + mt * 16 + g;
                    int jl = wn * 32 + nt * 8 + tg * 2;
                    int jg = nblk * BN + jl;
                    float* out = (jg < 256) ? g_Q : ((jg < 512) ? g_K : g_V);
                    int j2 = jg & 255;
                    int h = j2 >> 5, f = j2 & 31;
                    float b0 = bias_s[jl], b1 = bias_s[jl + 1];
                    size_t i0 = (((size_t)t0 * NH + h) * NJ + njoint) * FD + f;
                    float2 v0 = make_float2(acc[mt][nt][0] + b0, acc[mt][nt][1] + b1);
                    *(float2*)&out[i0] = v0;
                    size_t i1 = (((size_t)(t0 + 8) * NH + h) * NJ + njoint) * FD + f;
                    float2 v1 = make_float2(acc[mt][nt][2] + b0, acc[mt][nt][3] + b1);
                    *(float2*)&out[i1] = v1;
                    acc[mt][nt][0] = acc[mt][nt][1] = acc[mt][nt][2] = acc[mt][nt][3] = 0.f;
                }
        }

        if (c < 511) {
            // fill the *other* stage (safe: last read of it was before prev sync)
            float* dst = As + ((c + 1) & 1) * BM * APAD;
#pragma unroll
            for (int i = 0; i < 4; ++i) {
                int lin = tid + 256 * i;
                int row = lin >> 3, c4 = lin & 7;
                float4 v = rN[i];
                v.x = __uint_as_float(f2tf32(v.x));
                v.y = __uint_as_float(f2tf32(v.y));
                v.z = __uint_as_float(f2tf32(v.z));
                v.w = __uint_as_float(f2tf32(v.w));
                *(float4*)&dst[row * APAD + c4 * 4] = v;
            }
            __syncthreads();
        }
    }
}

// -------- K2: per-token attention + residual + LayerNorm --------------------
// grid = 8192 CTAs of 256 threads; warp h handles head h, lane n handles row n.
__global__ void __launch_bounds__(256, 2)
attn_ln_kernel(const float* __restrict__ x, const float* __restrict__ gamma,
               const float* __restrict__ beta, float* __restrict__ y) {
    extern __shared__ float sm2[];
    float* qs   = sm2;                 // [192][36] padded (row = h*24+n)
    float* ks   = qs + 192 * 36;       // [6144] flat [h][m][f]
    float* vs   = ks + 6144;           // [6144]
    float* outs = vs + 6144;           // [24][260]
    float* red  = outs + 24 * 260;     // [16]

    const int t = blockIdx.x;
    const int tid = threadIdx.x;
    const int warp = tid >> 5, lane = tid & 31;

    const float* Qg = g_Q + (size_t)t * JD;
    const float* Kg = g_K + (size_t)t * JD;
    const float* Vg = g_V + (size_t)t * JD;

    for (int i = tid; i < 1536; i += 256) {        // q: padded rows of 32
        float4 v = *(const float4*)&Qg[i * 4];
        int r = i >> 3, c4 = i & 7;
        *(float4*)&qs[r * 36 + c4 * 4] = v;
    }
    for (int i = tid; i < 1536; i += 256)
        *(float4*)&ks[i * 4] = *(const float4*)&Kg[i * 4];
    for (int i = tid; i < 1536; i += 256)
        *(float4*)&vs[i * 4] = *(const float4*)&Vg[i * 4];
    __syncthreads();

    if (lane < NJ) {
        const int h = warp, n = lane;
        const float scale = 0.17677669529663687f;  // 1/sqrt(32)
        float q[32];
        int r = h * NJ + n;
#pragma unroll
        for (int f4 = 0; f4 < 8; ++f4) {
            float4 v = *(const float4*)&qs[r * 36 + f4 * 4];
            q[f4 * 4 + 0] = v.x * scale; q[f4 * 4 + 1] = v.y * scale;
            q[f4 * 4 + 2] = v.z * scale; q[f4 * 4 + 3] = v.w * scale;
        }
        float sc[NJ];
        const float* kh = ks + h * (NJ * FD);
#pragma unroll
        for (int m = 0; m < NJ; ++m) {
            float s = 0.f;
            const float4* kr = (const float4*)(kh + m * FD);
#pragma unroll
            for (int f4 = 0; f4 < 8; ++f4) {
                float4 kv = kr[f4];
                s += q[f4 * 4 + 0] * kv.x + q[f4 * 4 + 1] * kv.y
                   + q[f4 * 4 + 2] * kv.z + q[f4 * 4 + 3] * kv.w;
            }
            sc[m] = s;
        }
        float mx = sc[0];
#pragma unroll
        for (int m = 1; m < NJ; ++m) mx = fmaxf(mx, sc[m]);
        float sum = 0.f;
#pragma unroll
        for (int m = 0; m < NJ; ++m) { sc[m] = __expf(sc[m] - mx); sum += sc[m]; }
        float inv = 1.f / sum;

        float o[32];
#pragma unroll
        for (int f = 0; f < 32; ++f) o[f] = 0.f;
        const float* vh = vs + h * (NJ * FD);
#pragma unroll
        for (int m = 0; m < NJ; ++m) {
            float a = sc[m] * inv;
            const float4* vr = (const float4*)(vh + m * FD);
#pragma unroll
            for (int f4 = 0; f4 < 8; ++f4) {
                float4 vv = vr[f4];
                o[f4 * 4 + 0] += a * vv.x; o[f4 * 4 + 1] += a * vv.y;
                o[f4 * 4 + 2] += a * vv.z; o[f4 * 4 + 3] += a * vv.w;
            }
        }
#pragma unroll
        for (int f = 0; f < 32; ++f) outs[n * 260 + h * 32 + f] = o[f];
    }
    __syncthreads();

    // residual + LayerNorm over 6144
    const float* xg = x + (size_t)t * JD;
    float yv[24];
    float s1 = 0.f, s2 = 0.f;
#pragma unroll
    for (int i = 0; i < 24; ++i) {
        int idx = i * 256 + tid;
        float v = xg[idx] + outs[(idx >> 8) * 260 + (idx & 255)];
        yv[i] = v; s1 += v; s2 += v * v;
    }
#pragma unroll
    for (int o = 16; o; o >>= 1) {
        s1 += __shfl_xor_sync(0xffffffffu, s1, o);
        s2 += __shfl_xor_sync(0xffffffffu, s2, o);
    }
    if (lane == 0) { red[warp] = s1; red[warp + 8] = s2; }
    __syncthreads();
    float S1 = 0.f, S2 = 0.f;
#pragma unroll
    for (int w = 0; w < 8; ++w) { S1 += red[w]; S2 += red[w + 8]; }
    const float mu = S1 * (1.0f / JD);
    const float var = S2 * (1.0f / JD) - mu * mu;
    const float rstd = rsqrtf(var + 1e-5f);
    float* yt = y + (size_t)t * JD;
#pragma unroll
    for (int i = 0; i < 24; ++i) {
        int idx = i * 256 + tid;
        yt[idx] = (yv[i] - mu) * rstd * gamma[idx] + beta[idx];
    }
}

// ---------------------------------------------------------------------------
extern "C" void kernel_launch(void* const* d_in, const int* in_sizes, int n_in,
                              void* d_out, int out_size) {
    const float* x     = (const float*)d_in[0];
    const float* Wq    = (const float*)d_in[1];
    const float* bq    = (const float*)d_in[2];
    const float* Wk    = (const float*)d_in[3];
    const float* bk    = (const float*)d_in[4];
    const float* Wv    = (const float*)d_in[5];
    const float* bv    = (const float*)d_in[6];
    const float* gamma = (const float*)d_in[7];
    const float* beta  = (const float*)d_in[8];
    float* y = (float*)d_out;

    cudaFuncSetAttribute(qkv_gemm_kernel, cudaFuncAttributeMaxDynamicSharedMemorySize, SMEM1);
    cudaFuncSetAttribute(attn_ln_kernel,  cudaFuncAttributeMaxDynamicSharedMemorySize, SMEM2);

    prep_w_kernel<<<4608, 256>>>(Wq, Wk, Wv);
    prep_b_kernel<<<72, 256>>>(bq, bk, bv);
    qkv_gemm_kernel<<<NJ * 6, 256, SMEM1>>>(x);
    attn_ln_kernel<<<T_TOK, 256, SMEM2>>>(x, gamma, beta, y);
}